// round 12
// baseline (speedup 1.0000x reference)
#include <cuda_runtime.h>
#include <math.h>

#define B 4
#define L 2048
#define D 2048
#define NBLK 512       // persistent-kernel grid (<= 148*4 for residency)
#define ICK 64         // col-term i-chunks (32 rows each)
#define DT_STEP 0.01f
#define DEG 8

// ---- scratch (device globals, no allocation allowed) ----
__device__ float g_xmean[B*D];         // 32 KB
__device__ float g_t[B*D];             // 32 KB
__device__ float g_colpart[ICK*B*D];   // 2 MB
__device__ float g_delta[B*D];         // 32 KB
__device__ float g_mono[DEG+1];        // monomial coeffs of sum c_i T_i

// ---- grid barrier (generation-based: replay-safe, never reset gen) ----
__device__ unsigned g_bar_count = 0;
__device__ unsigned g_bar_gen   = 0;

__device__ __forceinline__ void gridbar() {
    __syncthreads();
    if (threadIdx.x == 0) {
        __threadfence();
        unsigned gen = *(volatile unsigned*)&g_bar_gen;
        unsigned old = atomicAdd(&g_bar_count, 1u);
        if (old == NBLK - 1) {
            g_bar_count = 0;
            __threadfence();
            *(volatile unsigned*)&g_bar_gen = gen + 1;
        } else {
            while (*(volatile unsigned*)&g_bar_gen == gen) {}
        }
        __threadfence();
    }
    __syncthreads();
}

// ============ Fused mid chain ============
__global__ void __launch_bounds__(256, 4) k_mid(const float* __restrict__ x,
                                                const float* __restrict__ ju,
                                                const float* __restrict__ hp,
                                                const float* __restrict__ rd,
                                                const float* __restrict__ cf) {
    __shared__ float s_t[B][32];
    __shared__ float s_part[8][4];
    __shared__ float s_col[16][17];
    __shared__ float4 s_w[8][4];
    const int bid = blockIdx.x;
    const int t   = threadIdx.x;
    const int w = t >> 5, lane = t & 31;

    // ---------- one-time: Chebyshev -> monomial coefficient conversion ----------
    if (bid == NBLK-1 && t == 32) {
        float tp[9], tc[9], tn[9], m[9];
        #pragma unroll
        for (int i = 0; i < 9; ++i) { tp[i]=0.f; tc[i]=0.f; m[i]=0.f; }
        tp[0] = 1.f;              // T0
        tc[1] = 1.f;              // T1
        m[0] = cf[0];
        m[1] = cf[1];
        for (int n = 2; n <= DEG; ++n) {
            for (int i = 0; i < 9; ++i)
                tn[i] = (i ? 2.f*tc[i-1] : 0.f) - tp[i];
            float c = cf[n];
            for (int i = 0; i < 9; ++i) m[i] += c*tn[i];
            for (int i = 0; i < 9; ++i) { tp[i]=tc[i]; tc[i]=tn[i]; }
        }
        for (int i = 0; i < 9; ++i) g_mono[i] = m[i];
    }

    // ---------- P0: full-L column mean, one (b, 16-col) slab per block ----------
    {
        int b    = bid >> 7;           // 0..3
        int dcol = (bid & 127) * 16;   // 16-float slab
        int lsub = t >> 2;             // 0..63
        int c4   = t & 3;              // float4 within slab
        const float4* xp = (const float4*)x;
        size_t base = (((size_t)b*L + lsub)*D + dcol + c4*4) >> 2;
        float4 acc = make_float4(0.f,0.f,0.f,0.f);
        #pragma unroll 4               // cap front-batched MLP -> less cross-CTA spread
        for (int it = 0; it < 32; ++it) {
            float4 v = xp[base + (size_t)it*64*(D/4)];
            acc.x += v.x; acc.y += v.y; acc.z += v.z; acc.w += v.w;
        }
        #pragma unroll
        for (int off = 4; off <= 16; off <<= 1) {
            acc.x += __shfl_xor_sync(0xFFFFFFFFu, acc.x, off);
            acc.y += __shfl_xor_sync(0xFFFFFFFFu, acc.y, off);
            acc.z += __shfl_xor_sync(0xFFFFFFFFu, acc.z, off);
            acc.w += __shfl_xor_sync(0xFFFFFFFFu, acc.w, off);
        }
        if (lane < 4) s_w[w][lane] = acc;
        __syncthreads();
        if (t < 4) {
            float4 s = make_float4(0.f,0.f,0.f,0.f);
            #pragma unroll
            for (int ww = 0; ww < 8; ++ww) {
                float4 v = s_w[ww][t];
                s.x += v.x; s.y += v.y; s.z += v.z; s.w += v.w;
            }
            const float inv = 1.0f/(float)L;
            s.x *= inv; s.y *= inv; s.z *= inv; s.w *= inv;
            *(float4*)&g_xmean[b*D + dcol + t*4] = s;
        }
    }
    gridbar();

    // ---------- P2: t[b,i] = sum_j hp[i,j]*xmean[b,j]  (4 rows/block, 2 warps/row) ----------
    {
        int row  = bid*4 + (w >> 1);
        int half = w & 1;
        const float4* hr = (const float4*)(hp + (size_t)row*D);
        const float4* m0 = (const float4*)(g_xmean + 0*D);
        const float4* m1 = (const float4*)(g_xmean + 1*D);
        const float4* m2 = (const float4*)(g_xmean + 2*D);
        const float4* m3 = (const float4*)(g_xmean + 3*D);
        float a0=0.f,a1=0.f,a2=0.f,a3=0.f;
        #pragma unroll
        for (int it = 0; it < 8; ++it) {
            int j4 = half*256 + it*32 + lane;
            float4 hv = hr[j4];
            float4 v0 = m0[j4], v1 = m1[j4], v2 = m2[j4], v3 = m3[j4];
            a0 += hv.x*v0.x + hv.y*v0.y + hv.z*v0.z + hv.w*v0.w;
            a1 += hv.x*v1.x + hv.y*v1.y + hv.z*v1.z + hv.w*v1.w;
            a2 += hv.x*v2.x + hv.y*v2.y + hv.z*v2.z + hv.w*v2.w;
            a3 += hv.x*v3.x + hv.y*v3.y + hv.z*v3.z + hv.w*v3.w;
        }
        #pragma unroll
        for (int off = 16; off; off >>= 1) {
            a0 += __shfl_xor_sync(0xFFFFFFFFu, a0, off);
            a1 += __shfl_xor_sync(0xFFFFFFFFu, a1, off);
            a2 += __shfl_xor_sync(0xFFFFFFFFu, a2, off);
            a3 += __shfl_xor_sync(0xFFFFFFFFu, a3, off);
        }
        if (lane == 0) { s_part[w][0]=a0; s_part[w][1]=a1; s_part[w][2]=a2; s_part[w][3]=a3; }
        __syncthreads();
        if (t < 16) {
            int rowin = t >> 2, b = t & 3;
            float s = s_part[rowin*2][b] + s_part[rowin*2+1][b];
            g_t[b*D + bid*4 + rowin] = s;
        }
    }
    gridbar();

    // ---------- P3: col partials: sum_{i in chunk} t[b,i]*ju[i,k] ----------
    {
        int ktile = bid >> 6;
        int ick   = bid & 63;
        int i0    = ick*32;
        if (t < B*32) {
            int b = t >> 5, ii = t & 31;
            s_t[b][ii] = g_t[b*D + i0 + ii];
        }
        __syncthreads();
        int k = ktile*256 + t;
        float a0=0.f,a1=0.f,a2=0.f,a3=0.f;
        #pragma unroll
        for (int ii = 0; ii < 32; ++ii) {
            float v = ju[(size_t)(i0+ii)*D + k];
            a0 += s_t[0][ii]*v;
            a1 += s_t[1][ii]*v;
            a2 += s_t[2][ii]*v;
            a3 += s_t[3][ii]*v;
        }
        g_colpart[(size_t)(ick*B + 0)*D + k] = a0;
        g_colpart[(size_t)(ick*B + 1)*D + k] = a1;
        g_colpart[(size_t)(ick*B + 2)*D + k] = a2;
        g_colpart[(size_t)(ick*B + 3)*D + k] = a3;
    }
    gridbar();

    // ---------- P4: row dots + parallel col-sum + finalize delta ----------
    {
        int row  = bid*4 + (w >> 1);
        int half = w & 1;
        const float4* jr = (const float4*)(ju + (size_t)row*D);
        const float4* t0 = (const float4*)(g_t + 0*D);
        const float4* t1 = (const float4*)(g_t + 1*D);
        const float4* t2 = (const float4*)(g_t + 2*D);
        const float4* t3 = (const float4*)(g_t + 3*D);
        float a0=0.f,a1=0.f,a2=0.f,a3=0.f;
        #pragma unroll
        for (int it = 0; it < 8; ++it) {
            int j4 = half*256 + it*32 + lane;
            float4 jv = jr[j4];
            float4 v0 = t0[j4], v1 = t1[j4], v2 = t2[j4], v3 = t3[j4];
            a0 += jv.x*v0.x + jv.y*v0.y + jv.z*v0.z + jv.w*v0.w;
            a1 += jv.x*v1.x + jv.y*v1.y + jv.z*v1.z + jv.w*v1.w;
            a2 += jv.x*v2.x + jv.y*v2.y + jv.z*v2.z + jv.w*v2.w;
            a3 += jv.x*v3.x + jv.y*v3.y + jv.z*v3.z + jv.w*v3.w;
        }
        #pragma unroll
        for (int off = 16; off; off >>= 1) {
            a0 += __shfl_xor_sync(0xFFFFFFFFu, a0, off);
            a1 += __shfl_xor_sync(0xFFFFFFFFu, a1, off);
            a2 += __shfl_xor_sync(0xFFFFFFFFu, a2, off);
            a3 += __shfl_xor_sync(0xFFFFFFFFu, a3, off);
        }
        if (lane == 0) { s_part[w][0]=a0; s_part[w][1]=a1; s_part[w][2]=a2; s_part[w][3]=a3; }

        // parallel colpart reduction
        {
            int p = t >> 4;          // 0..15 pair (rowin<<2)|b
            int g = t & 15;          // chunk group of 4
            int b = p & 3, rowin = p >> 2;
            int k = bid*4 + rowin;
            float s = 0.f;
            #pragma unroll
            for (int c = 0; c < 4; ++c)
                s += g_colpart[(size_t)((g*4+c)*B + b)*D + k];
            s_col[p][g] = s;
        }
        __syncthreads();
        if (t < 16) {
            int rowin = t >> 2, b = t & 3;
            int k = bid*4 + rowin;
            float rowdot = s_part[rowin*2][b] + s_part[rowin*2+1][b];
            float col = 0.f;
            #pragma unroll
            for (int g = 0; g < 16; ++g) col += s_col[t][g];
            float rv = rd[k];
            float r = (rv > 20.f) ? rv : log1pf(expf(rv));
            g_delta[b*D + k] = DT_STEP * (rowdot - col - r*g_t[b*D + k]);
        }
    }
}

// ============ degree-8 polynomial via even/odd Horner ============
__device__ __forceinline__ float poly_eval(float xn, const float* __restrict__ m) {
    float u  = xn*xn;
    float pe = fmaf(fmaf(fmaf(fmaf(m[8],u,m[6]),u,m[4]),u,m[2]),u,m[0]);
    float po = fmaf(fmaf(fmaf(m[7],u,m[5]),u,m[3]),u,m[1]);
    return fmaf(xn, po, pe);
}

// ============ Main fused pass: 8 rows/block, 2-row-batched reductions ============
__global__ void __launch_bounds__(256) k_main(const float* __restrict__ x,
                                              float* __restrict__ out) {
    __shared__ float s_red[8][2];
    __shared__ float s_tot[2];
    int b = blockIdx.y;
    int tid = threadIdx.x;
    int warp = tid >> 5, lane = tid & 31;

    const float4* dp = (const float4*)(g_delta + b*D);
    float4 d0 = dp[tid];
    float4 d1 = dp[tid + 256];
    float m[DEG+1];
    #pragma unroll
    for (int i = 0; i <= DEG; ++i) m[i] = g_mono[i];

    size_t row0 = ((size_t)b*L + blockIdx.x*8)*D;

    #pragma unroll
    for (int it = 0; it < 4; ++it) {
        const float4* xpa = (const float4*)(x + row0 + (size_t)(it*2  )*D);
        const float4* xpb = (const float4*)(x + row0 + (size_t)(it*2+1)*D);
        float4*       opa = (float4*)(out + row0 + (size_t)(it*2  )*D);
        float4*       opb = (float4*)(out + row0 + (size_t)(it*2+1)*D);

        // load both rows together (doubled MLP)
        float4 a0 = xpa[tid], a1 = xpa[tid + 256];
        float4 b0 = xpb[tid], b1 = xpb[tid + 256];
        a0.x += d0.x; a0.y += d0.y; a0.z += d0.z; a0.w += d0.w;
        a1.x += d1.x; a1.y += d1.y; a1.z += d1.z; a1.w += d1.w;
        b0.x += d0.x; b0.y += d0.y; b0.z += d0.z; b0.w += d0.w;
        b1.x += d1.x; b1.y += d1.y; b1.z += d1.z; b1.w += d1.w;

        float sqa = a0.x*a0.x + a0.y*a0.y + a0.z*a0.z + a0.w*a0.w
                  + a1.x*a1.x + a1.y*a1.y + a1.z*a1.z + a1.w*a1.w;
        float sqb = b0.x*b0.x + b0.y*b0.y + b0.z*b0.z + b0.w*b0.w
                  + b1.x*b1.x + b1.y*b1.y + b1.z*b1.z + b1.w*b1.w;
        #pragma unroll
        for (int off = 16; off; off >>= 1) {
            sqa += __shfl_xor_sync(0xFFFFFFFFu, sqa, off);
            sqb += __shfl_xor_sync(0xFFFFFFFFu, sqb, off);
        }
        if (lane == 0) { s_red[warp][0] = sqa; s_red[warp][1] = sqb; }
        __syncthreads();
        if (warp == 0) {
            // lane = w*2 + which for lane<16
            float v = (lane < 16) ? s_red[lane >> 1][lane & 1] : 0.f;
            #pragma unroll
            for (int off = 2; off <= 8; off <<= 1)
                v += __shfl_xor_sync(0xFFFFFFFFu, v, off);
            if (lane < 2) s_tot[lane] = v;
        }
        __syncthreads();
        float inva = rsqrtf(fmaxf(s_tot[0], 1e-8f));
        float invb = rsqrtf(fmaxf(s_tot[1], 1e-8f));

        float4 ra0, ra1, rb0, rb1;
        ra0.x = a0.x + 0.1f*poly_eval(a0.x*inva, m);
        ra0.y = a0.y + 0.1f*poly_eval(a0.y*inva, m);
        ra0.z = a0.z + 0.1f*poly_eval(a0.z*inva, m);
        ra0.w = a0.w + 0.1f*poly_eval(a0.w*inva, m);
        ra1.x = a1.x + 0.1f*poly_eval(a1.x*inva, m);
        ra1.y = a1.y + 0.1f*poly_eval(a1.y*inva, m);
        ra1.z = a1.z + 0.1f*poly_eval(a1.z*inva, m);
        ra1.w = a1.w + 0.1f*poly_eval(a1.w*inva, m);
        rb0.x = b0.x + 0.1f*poly_eval(b0.x*invb, m);
        rb0.y = b0.y + 0.1f*poly_eval(b0.y*invb, m);
        rb0.z = b0.z + 0.1f*poly_eval(b0.z*invb, m);
        rb0.w = b0.w + 0.1f*poly_eval(b0.w*invb, m);
        rb1.x = b1.x + 0.1f*poly_eval(b1.x*invb, m);
        rb1.y = b1.y + 0.1f*poly_eval(b1.y*invb, m);
        rb1.z = b1.z + 0.1f*poly_eval(b1.z*invb, m);
        rb1.w = b1.w + 0.1f*poly_eval(b1.w*invb, m);
        __stcs(&opa[tid],       ra0);
        __stcs(&opa[tid + 256], ra1);
        __stcs(&opb[tid],       rb0);
        __stcs(&opb[tid + 256], rb1);
    }
}

extern "C" void kernel_launch(void* const* d_in, const int* in_sizes, int n_in,
                              void* d_out, int out_size) {
    const float* x   = (const float*)d_in[0];   // [B, L, D]
    const float* ju  = (const float*)d_in[1];   // [D, D]
    const float* rd  = (const float*)d_in[2];   // [D]
    const float* hp  = (const float*)d_in[3];   // [D, D]
    const float* cf  = (const float*)d_in[4];   // [9]
    float* out = (float*)d_out;
    (void)in_sizes; (void)n_in; (void)out_size;

    k_mid<<<NBLK, 256>>>(x, ju, hp, rd, cf);
    k_main<<<dim3(L/8, B), 256>>>(x, out);
}

// round 13
// speedup vs baseline: 1.3464x; 1.3464x over previous
#include <cuda_runtime.h>
#include <math.h>

#define B 4
#define L 2048
#define D 2048
#define NBLK 512       // persistent-kernel grid (<= 148*4 for residency)
#define ICK 64         // col-term i-chunks (32 rows each)
#define NKT 8          // k-tiles of 256 cols
#define DT_STEP 0.01f
#define DEG 8

// ---- scratch (device globals, no allocation allowed) ----
__device__ float g_xmean[B*D];         // 32 KB
__device__ float g_t[B*D];             // 32 KB
__device__ float g_colpart[ICK*B*D];   // 2 MB
__device__ float g_rowpart[NKT*B*D];   // 256 KB
__device__ float g_delta[B*D];         // 32 KB
__device__ float g_mono[DEG+1];        // monomial coeffs of sum c_i T_i

// ---- grid barrier (generation-based: replay-safe, never reset gen) ----
__device__ unsigned g_bar_count = 0;
__device__ unsigned g_bar_gen   = 0;

__device__ __forceinline__ void gridbar() {
    __syncthreads();
    if (threadIdx.x == 0) {
        __threadfence();
        unsigned gen = *(volatile unsigned*)&g_bar_gen;
        unsigned old = atomicAdd(&g_bar_count, 1u);
        if (old == NBLK - 1) {
            g_bar_count = 0;
            __threadfence();
            *(volatile unsigned*)&g_bar_gen = gen + 1;
        } else {
            while (*(volatile unsigned*)&g_bar_gen == gen) {}
        }
        __threadfence();
    }
    __syncthreads();
}

// ============ Fused mid chain ============
__global__ void __launch_bounds__(256, 4) k_mid(const float* __restrict__ x,
                                                const float* __restrict__ ju,
                                                const float* __restrict__ hp,
                                                const float* __restrict__ rd,
                                                const float* __restrict__ cf) {
    __shared__ float s_ti[B][32];
    __shared__ float s_tk[B][256];
    __shared__ float s_part[8][4];
    __shared__ float4 s_w[8][4];
    const int bid = blockIdx.x;
    const int t   = threadIdx.x;
    const int w = t >> 5, lane = t & 31;

    // ---------- one-time: Chebyshev -> monomial coefficient conversion ----------
    if (bid == NBLK-1 && t == 32) {
        float tp[9], tc[9], tn[9], m[9];
        #pragma unroll
        for (int i = 0; i < 9; ++i) { tp[i]=0.f; tc[i]=0.f; m[i]=0.f; }
        tp[0] = 1.f;              // T0
        tc[1] = 1.f;              // T1
        m[0] = cf[0];
        m[1] = cf[1];
        for (int n = 2; n <= DEG; ++n) {
            for (int i = 0; i < 9; ++i)
                tn[i] = (i ? 2.f*tc[i-1] : 0.f) - tp[i];
            float c = cf[n];
            for (int i = 0; i < 9; ++i) m[i] += c*tn[i];
            for (int i = 0; i < 9; ++i) { tp[i]=tc[i]; tc[i]=tn[i]; }
        }
        for (int i = 0; i < 9; ++i) g_mono[i] = m[i];
    }

    // ---------- P0: full-L column mean, one (b, 16-col) slab per block ----------
    {
        int b    = bid >> 7;           // 0..3
        int dcol = (bid & 127) * 16;   // 16-float slab
        int lsub = t >> 2;             // 0..63
        int c4   = t & 3;              // float4 within slab
        const float4* xp = (const float4*)x;
        size_t base = (((size_t)b*L + lsub)*D + dcol + c4*4) >> 2;
        float4 acc = make_float4(0.f,0.f,0.f,0.f);
        #pragma unroll                 // FULL unroll: deep MLP is what P0 needs
        for (int it = 0; it < 32; ++it) {
            float4 v = xp[base + (size_t)it*64*(D/4)];
            acc.x += v.x; acc.y += v.y; acc.z += v.z; acc.w += v.w;
        }
        #pragma unroll
        for (int off = 4; off <= 16; off <<= 1) {
            acc.x += __shfl_xor_sync(0xFFFFFFFFu, acc.x, off);
            acc.y += __shfl_xor_sync(0xFFFFFFFFu, acc.y, off);
            acc.z += __shfl_xor_sync(0xFFFFFFFFu, acc.z, off);
            acc.w += __shfl_xor_sync(0xFFFFFFFFu, acc.w, off);
        }
        if (lane < 4) s_w[w][lane] = acc;
        __syncthreads();
        if (t < 4) {
            float4 s = make_float4(0.f,0.f,0.f,0.f);
            #pragma unroll
            for (int ww = 0; ww < 8; ++ww) {
                float4 v = s_w[ww][t];
                s.x += v.x; s.y += v.y; s.z += v.z; s.w += v.w;
            }
            const float inv = 1.0f/(float)L;
            s.x *= inv; s.y *= inv; s.z *= inv; s.w *= inv;
            *(float4*)&g_xmean[b*D + dcol + t*4] = s;
        }
    }
    gridbar();

    // ---------- P2: t[b,i] = sum_j hp[i,j]*xmean[b,j]  (4 rows/block, 2 warps/row) ----------
    {
        int row  = bid*4 + (w >> 1);
        int half = w & 1;
        const float4* hr = (const float4*)(hp + (size_t)row*D);
        const float4* m0 = (const float4*)(g_xmean + 0*D);
        const float4* m1 = (const float4*)(g_xmean + 1*D);
        const float4* m2 = (const float4*)(g_xmean + 2*D);
        const float4* m3 = (const float4*)(g_xmean + 3*D);
        float a0=0.f,a1=0.f,a2=0.f,a3=0.f;
        #pragma unroll
        for (int it = 0; it < 8; ++it) {
            int j4 = half*256 + it*32 + lane;
            float4 hv = hr[j4];
            float4 v0 = m0[j4], v1 = m1[j4], v2 = m2[j4], v3 = m3[j4];
            a0 += hv.x*v0.x + hv.y*v0.y + hv.z*v0.z + hv.w*v0.w;
            a1 += hv.x*v1.x + hv.y*v1.y + hv.z*v1.z + hv.w*v1.w;
            a2 += hv.x*v2.x + hv.y*v2.y + hv.z*v2.z + hv.w*v2.w;
            a3 += hv.x*v3.x + hv.y*v3.y + hv.z*v3.z + hv.w*v3.w;
        }
        #pragma unroll
        for (int off = 16; off; off >>= 1) {
            a0 += __shfl_xor_sync(0xFFFFFFFFu, a0, off);
            a1 += __shfl_xor_sync(0xFFFFFFFFu, a1, off);
            a2 += __shfl_xor_sync(0xFFFFFFFFu, a2, off);
            a3 += __shfl_xor_sync(0xFFFFFFFFu, a3, off);
        }
        if (lane == 0) { s_part[w][0]=a0; s_part[w][1]=a1; s_part[w][2]=a2; s_part[w][3]=a3; }
        __syncthreads();
        if (t < 16) {
            int rowin = t >> 2, b = t & 3;
            float s = s_part[rowin*2][b] + s_part[rowin*2+1][b];
            g_t[b*D + bid*4 + rowin] = s;
        }
    }
    gridbar();

    // ---------- P3: tile (ick, ktile): col-dot partials AND row-dot partials ----------
    {
        int ktile = bid >> 6;      // 0..7
        int ick   = bid & 63;      // 0..63
        int i0    = ick*32;
        int kbase = ktile*256;
        // stage t-slices in shared
        if (t < B*32) {
            int b = t >> 5, ii = t & 31;
            s_ti[b][ii] = g_t[b*D + i0 + ii];
        }
        #pragma unroll
        for (int rep = 0; rep < 4; ++rep) {
            int idx = rep*256 + t;
            s_tk[idx >> 8][idx & 255] = g_t[(idx >> 8)*D + kbase + (idx & 255)];
        }
        __syncthreads();

        // pass 1: col dots (thread per column, loop rows)
        {
            int k = kbase + t;
            float a0=0.f,a1=0.f,a2=0.f,a3=0.f;
            #pragma unroll
            for (int ii = 0; ii < 32; ++ii) {
                float v = ju[(size_t)(i0+ii)*D + k];
                a0 += s_ti[0][ii]*v;
                a1 += s_ti[1][ii]*v;
                a2 += s_ti[2][ii]*v;
                a3 += s_ti[3][ii]*v;
            }
            g_colpart[(size_t)(ick*B + 0)*D + k] = a0;
            g_colpart[(size_t)(ick*B + 1)*D + k] = a1;
            g_colpart[(size_t)(ick*B + 2)*D + k] = a2;
            g_colpart[(size_t)(ick*B + 3)*D + k] = a3;
        }

        // pass 2: row-dot partials (warp per 4 rows; tile is L1-hot from pass 1)
        {
            float acc[4][4];
            #pragma unroll
            for (int j = 0; j < 4; ++j)
                #pragma unroll
                for (int b = 0; b < 4; ++b) acc[j][b] = 0.f;
            const float4* tk0 = (const float4*)&s_tk[0][0];
            const float4* tk1 = (const float4*)&s_tk[1][0];
            const float4* tk2 = (const float4*)&s_tk[2][0];
            const float4* tk3 = (const float4*)&s_tk[3][0];
            #pragma unroll
            for (int j = 0; j < 4; ++j) {
                int row = i0 + w*4 + j;
                const float4* jr = (const float4*)(ju + (size_t)row*D + kbase);
                #pragma unroll
                for (int h = 0; h < 2; ++h) {
                    int c4 = h*32 + lane;
                    float4 jv = jr[c4];
                    float4 v0 = tk0[c4], v1 = tk1[c4], v2 = tk2[c4], v3 = tk3[c4];
                    acc[j][0] += jv.x*v0.x + jv.y*v0.y + jv.z*v0.z + jv.w*v0.w;
                    acc[j][1] += jv.x*v1.x + jv.y*v1.y + jv.z*v1.z + jv.w*v1.w;
                    acc[j][2] += jv.x*v2.x + jv.y*v2.y + jv.z*v2.z + jv.w*v2.w;
                    acc[j][3] += jv.x*v3.x + jv.y*v3.y + jv.z*v3.z + jv.w*v3.w;
                }
            }
            #pragma unroll
            for (int off = 16; off; off >>= 1)
                #pragma unroll
                for (int j = 0; j < 4; ++j)
                    #pragma unroll
                    for (int b = 0; b < 4; ++b)
                        acc[j][b] += __shfl_xor_sync(0xFFFFFFFFu, acc[j][b], off);
            if (lane < 16) {
                int j = lane >> 2, b = lane & 3;
                g_rowpart[(size_t)(ktile*B + b)*D + i0 + w*4 + j] = acc[j][b];
            }
        }
    }
    gridbar();

    // ---------- P4: tiny combine: delta = DT*(rowdot - colsum - softplus(r)*t) ----------
    {
        int idx = bid*16 + (t >> 4);     // 0..8191 target (b,k)
        int s   = t & 15;
        int b = idx >> 11, k = idx & (D-1);
        float v = 0.f;
        #pragma unroll
        for (int c = 0; c < 4; ++c)
            v -= g_colpart[(size_t)((s*4+c)*B + b)*D + k];
        if (s < NKT)
            v += g_rowpart[(size_t)(s*B + b)*D + k];
        #pragma unroll
        for (int off = 1; off <= 8; off <<= 1)
            v += __shfl_xor_sync(0xFFFFFFFFu, v, off);   // sums within 16-group
        if (s == 0) {
            float rv = rd[k];
            float r = (rv > 20.f) ? rv : log1pf(expf(rv));
            g_delta[b*D + k] = DT_STEP * (v - r*g_t[b*D + k]);
        }
    }
}

// ============ degree-8 polynomial via even/odd Horner ============
__device__ __forceinline__ float poly_eval(float xn, const float* __restrict__ m) {
    float u  = xn*xn;
    float pe = fmaf(fmaf(fmaf(fmaf(m[8],u,m[6]),u,m[4]),u,m[2]),u,m[0]);
    float po = fmaf(fmaf(fmaf(m[7],u,m[5]),u,m[3]),u,m[1]);
    return fmaf(xn, po, pe);
}

// ============ Main fused pass: 1 row per block (max parallelism, 32 regs) ============
__global__ void __launch_bounds__(256) k_main(const float* __restrict__ x,
                                              float* __restrict__ out) {
    __shared__ float s_red[9];
    int l = blockIdx.x, b = blockIdx.y;
    int tid = threadIdx.x;
    int warp = tid >> 5, lane = tid & 31;

    size_t base = ((size_t)b*L + l)*D;
    const float4* xp = (const float4*)(x + base);
    float4*       op = (float4*)(out + base);
    const float4* dp = (const float4*)(g_delta + b*D);

    float4 y0 = xp[tid];
    float4 y1 = xp[tid + 256];
    float4 d0 = dp[tid];
    float4 d1 = dp[tid + 256];
    y0.x += d0.x; y0.y += d0.y; y0.z += d0.z; y0.w += d0.w;
    y1.x += d1.x; y1.y += d1.y; y1.z += d1.z; y1.w += d1.w;

    float sq = y0.x*y0.x + y0.y*y0.y + y0.z*y0.z + y0.w*y0.w
             + y1.x*y1.x + y1.y*y1.y + y1.z*y1.z + y1.w*y1.w;
    #pragma unroll
    for (int off = 16; off; off >>= 1)
        sq += __shfl_xor_sync(0xFFFFFFFFu, sq, off);
    if (lane == 0) s_red[warp] = sq;
    __syncthreads();
    if (warp == 0) {
        float v = (lane < 8) ? s_red[lane] : 0.f;
        #pragma unroll
        for (int off = 4; off; off >>= 1)
            v += __shfl_xor_sync(0xFFFFFFFFu, v, off);
        if (lane == 0) s_red[8] = v;
    }
    __syncthreads();
    float inv = rsqrtf(fmaxf(s_red[8], 1e-8f));

    float m[DEG+1];
    #pragma unroll
    for (int i = 0; i <= DEG; ++i) m[i] = g_mono[i];

    float4 r0, r1;
    r0.x = y0.x + 0.1f*poly_eval(y0.x*inv, m);
    r0.y = y0.y + 0.1f*poly_eval(y0.y*inv, m);
    r0.z = y0.z + 0.1f*poly_eval(y0.z*inv, m);
    r0.w = y0.w + 0.1f*poly_eval(y0.w*inv, m);
    r1.x = y1.x + 0.1f*poly_eval(y1.x*inv, m);
    r1.y = y1.y + 0.1f*poly_eval(y1.y*inv, m);
    r1.z = y1.z + 0.1f*poly_eval(y1.z*inv, m);
    r1.w = y1.w + 0.1f*poly_eval(y1.w*inv, m);
    __stcs(&op[tid],       r0);
    __stcs(&op[tid + 256], r1);
}

extern "C" void kernel_launch(void* const* d_in, const int* in_sizes, int n_in,
                              void* d_out, int out_size) {
    const float* x   = (const float*)d_in[0];   // [B, L, D]
    const float* ju  = (const float*)d_in[1];   // [D, D]
    const float* rd  = (const float*)d_in[2];   // [D]
    const float* hp  = (const float*)d_in[3];   // [D, D]
    const float* cf  = (const float*)d_in[4];   // [9]
    float* out = (float*)d_out;
    (void)in_sizes; (void)n_in; (void)out_size;

    k_mid<<<NBLK, 256>>>(x, ju, hp, rd, cf);
    k_main<<<dim3(L, B), 256>>>(x, out);
}